// round 1
// baseline (speedup 1.0000x reference)
#include <cuda_runtime.h>
#include <math.h>

#define N 8192
#define EDIM 128
#define WFEAT 128
#define SLOPE 0.01f
#define NEGINF (-3.0e38f)

// ---------------- device scratch (no allocations allowed) ----------------
__device__ float g_h[(size_t)N * WFEAT];      // projected features (8192x128)
__device__ float g_fsrc[N];
__device__ float g_fdst[N];
__device__ float g_rowMax[N];
__device__ float g_rowInvZ[N];
__device__ float g_pmax[64 * WFEAT];          // pooling partials

// ---------------- K1: h = emb[inSen] @ W  (16 rows / block) ----------------
__global__ __launch_bounds__(128) void k1_proj(const int* __restrict__ inSen,
                                               const float* __restrict__ emb,
                                               const float* __restrict__ W) {
    __shared__ float Ws[64][128];   // 32 KB  (K-chunk of W)
    __shared__ float wv[16][64];    // 4 KB   (K-chunk of 16 gathered word vecs)
    __shared__ int   sIdx[16];

    const int tid = threadIdx.x;           // 0..127
    const int i0  = blockIdx.x * 16;

    if (tid < 16) sIdx[tid] = inSen[i0 + tid];
    __syncthreads();

    float acc[16];
#pragma unroll
    for (int r = 0; r < 16; r++) acc[r] = 0.f;

    const int r  = tid >> 3;               // 0..15
    const int p0 = (tid & 7) * 8;          // 0..56

    for (int kc = 0; kc < EDIM; kc += 64) {
        // load W chunk: rows kc..kc+63, all 128 cols (coalesced across tid)
#pragma unroll 8
        for (int dd = 0; dd < 64; dd++)
            Ws[dd][tid] = W[(size_t)(kc + dd) * WFEAT + tid];
        // load word-vector chunk
        {
            const float* er = emb + (size_t)sIdx[r] * EDIM + kc;
#pragma unroll
            for (int p = 0; p < 8; p++) wv[r][p0 + p] = er[p0 + p];
        }
        __syncthreads();
#pragma unroll 16
        for (int dd = 0; dd < 64; dd++) {
            const float w = Ws[dd][tid];
#pragma unroll
            for (int rr = 0; rr < 16; rr++) acc[rr] += wv[rr][dd] * w;
        }
        __syncthreads();
    }
#pragma unroll
    for (int rr = 0; rr < 16; rr++)
        g_h[(size_t)(i0 + rr) * WFEAT + tid] = acc[rr];
}

// ---------------- Kf: f_src / f_dst (one row per block of 128) -------------
__global__ __launch_bounds__(128) void kf_feat(const float* __restrict__ a_src,
                                               const float* __restrict__ a_dst) {
    const int i = blockIdx.x;
    const int tid = threadIdx.x;
    const float hv = g_h[(size_t)i * WFEAT + tid];
    float ps = hv * a_src[tid];
    float pd = hv * a_dst[tid];
#pragma unroll
    for (int off = 16; off > 0; off >>= 1) {
        ps += __shfl_xor_sync(0xffffffffu, ps, off);
        pd += __shfl_xor_sync(0xffffffffu, pd, off);
    }
    __shared__ float rs[4], rd[4];
    const int w = tid >> 5, l = tid & 31;
    if (l == 0) { rs[w] = ps; rd[w] = pd; }
    __syncthreads();
    if (tid == 0) g_fsrc[i] = rs[0] + rs[1] + rs[2] + rs[3];
    if (tid == 1) g_fdst[i] = rd[0] + rd[1] + rd[2] + rd[3];
}

// ---------------- K2: per-row softmax stats (max, 1/Z) ---------------------
__global__ __launch_bounds__(256) void k2_stats(const int* __restrict__ adj,
                                                const int* __restrict__ selfLinkP) {
    const int i   = blockIdx.x;
    const int tid = threadIdx.x;      // 256
    const int selfLink = *selfLinkP;
    const float si = g_fsrc[i];

    float v[32];
    float tm = NEGINF;
#pragma unroll
    for (int k = 0; k < 32; k++) {
        const int j = tid + (k << 8);
        int a = adj[(size_t)i * N + j];
        if (j == i) a += selfLink;
        const float x = si + g_fdst[j];
        const float e = (x >= 0.f) ? x : SLOPE * x;
        const float val = (a > 0) ? e : -1e9f;
        v[k] = val;
        tm = fmaxf(tm, val);
    }
    __shared__ float smax[8];
#pragma unroll
    for (int off = 16; off > 0; off >>= 1) tm = fmaxf(tm, __shfl_xor_sync(0xffffffffu, tm, off));
    if ((tid & 31) == 0) smax[tid >> 5] = tm;
    __syncthreads();
    if (tid < 32) {
        float z = (tid < 8) ? smax[tid] : NEGINF;
#pragma unroll
        for (int off = 4; off > 0; off >>= 1) z = fmaxf(z, __shfl_xor_sync(0xffffffffu, z, off));
        if (tid == 0) smax[0] = z;
    }
    __syncthreads();
    const float M = smax[0];

    float ts = 0.f;
#pragma unroll
    for (int k = 0; k < 32; k++) ts += __expf(v[k] - M);
    __shared__ float ssum[8];
#pragma unroll
    for (int off = 16; off > 0; off >>= 1) ts += __shfl_xor_sync(0xffffffffu, ts, off);
    if ((tid & 31) == 0) ssum[tid >> 5] = ts;
    __syncthreads();
    if (tid == 0) {
        float S = 0.f;
#pragma unroll
        for (int w = 0; w < 8; w++) S += ssum[w];
        g_rowMax[i]  = M;
        g_rowInvZ[i] = 1.0f / S;
    }
}

// ------- K3: fused attention materialization + sentence = att @ h ----------
// 64-row tile per CTA, K-chunks of 64, 256 threads, 4x8 micro-tile / thread.
#define BI 64
#define BJ 64
__global__ __launch_bounds__(256) void k3_fused(const int* __restrict__ adj,
                                                const int* __restrict__ selfLinkP,
                                                float* __restrict__ att_out,
                                                float* __restrict__ sen_out) {
    __shared__ float s_att[BI * BJ];            // 16 KB
    __shared__ float s_h[BJ * WFEAT];           // 32 KB (first 64 floats double as d-chunk)

    const int tid = threadIdx.x;                // 256
    const int i0  = blockIdx.x * BI;
    const int selfLink = *selfLinkP;

    const int tr = tid >> 4;                    // 0..15
    const int tc = tid & 15;                    // 0..15
    const int r0 = tr * 4;                      // rows of micro-tile (in tile)
    const int c0 = tc * 8;                      // cols of micro-tile (output feat)
    const int j0 = tc * 4;                      // stage-A column offset

    float s_i[4], m_i[4], iz[4];
#pragma unroll
    for (int q = 0; q < 4; q++) {
        const int gi = i0 + r0 + q;
        s_i[q] = g_fsrc[gi];
        m_i[q] = g_rowMax[gi];
        iz[q]  = g_rowInvZ[gi];
    }

    float4 accA[4], accB[4];
#pragma unroll
    for (int q = 0; q < 4; q++) {
        accA[q] = make_float4(0.f, 0.f, 0.f, 0.f);
        accB[q] = make_float4(0.f, 0.f, 0.f, 0.f);
    }

    for (int jc = 0; jc < N / BJ; jc++) {
        const int jbase = jc * BJ;

        // stage 0: d-chunk into first 64 floats of s_h
        if (tid < BJ) s_h[tid] = g_fdst[jbase + tid];
        __syncthreads();

        // stage A: compute 64x64 attention tile, write to smem + global
#pragma unroll
        for (int q = 0; q < 4; q++) {
            const int ii = r0 + q;
            const int gi = i0 + ii;
            const int4 a4 = *(const int4*)&adj[(size_t)gi * N + jbase + j0];
            int aarr[4] = {a4.x, a4.y, a4.z, a4.w};
            float vals[4];
#pragma unroll
            for (int p = 0; p < 4; p++) {
                const int j = jbase + j0 + p;
                int m = aarr[p] + ((j == gi) ? selfLink : 0);
                const float x = s_i[q] + s_h[j0 + p];
                const float e = (x >= 0.f) ? x : SLOPE * x;
                const float vv = (m > 0) ? e : -1e9f;
                vals[p] = __expf(vv - m_i[q]) * iz[q];
            }
            const float4 f4 = make_float4(vals[0], vals[1], vals[2], vals[3]);
            *(float4*)&s_att[ii * BJ + j0] = f4;
            *(float4*)&att_out[(size_t)gi * N + jbase + j0] = f4;
        }
        __syncthreads();

        // stage B: load h chunk (64x128) into smem
        {
            const float4* src = (const float4*)&g_h[(size_t)jbase * WFEAT];
            float4* dst = (float4*)s_h;
#pragma unroll
            for (int p = 0; p < 8; p++) dst[tid + p * 256] = src[tid + p * 256];
        }
        __syncthreads();

        // stage C: micro GEMM
#pragma unroll 8
        for (int jj = 0; jj < BJ; jj++) {
            const float a0 = s_att[(r0 + 0) * BJ + jj];
            const float a1 = s_att[(r0 + 1) * BJ + jj];
            const float a2 = s_att[(r0 + 2) * BJ + jj];
            const float a3 = s_att[(r0 + 3) * BJ + jj];
            const float4 hA = *(const float4*)&s_h[jj * WFEAT + c0];
            const float4 hB = *(const float4*)&s_h[jj * WFEAT + c0 + 4];

            accA[0].x += a0 * hA.x; accA[0].y += a0 * hA.y; accA[0].z += a0 * hA.z; accA[0].w += a0 * hA.w;
            accB[0].x += a0 * hB.x; accB[0].y += a0 * hB.y; accB[0].z += a0 * hB.z; accB[0].w += a0 * hB.w;
            accA[1].x += a1 * hA.x; accA[1].y += a1 * hA.y; accA[1].z += a1 * hA.z; accA[1].w += a1 * hA.w;
            accB[1].x += a1 * hB.x; accB[1].y += a1 * hB.y; accB[1].z += a1 * hB.z; accB[1].w += a1 * hB.w;
            accA[2].x += a2 * hA.x; accA[2].y += a2 * hA.y; accA[2].z += a2 * hA.z; accA[2].w += a2 * hA.w;
            accB[2].x += a2 * hB.x; accB[2].y += a2 * hB.y; accB[2].z += a2 * hB.z; accB[2].w += a2 * hB.w;
            accA[3].x += a3 * hA.x; accA[3].y += a3 * hA.y; accA[3].z += a3 * hA.z; accA[3].w += a3 * hA.w;
            accB[3].x += a3 * hB.x; accB[3].y += a3 * hB.y; accB[3].z += a3 * hB.z; accB[3].w += a3 * hB.w;
        }
        __syncthreads();
    }

    // write sentence tile
#pragma unroll
    for (int q = 0; q < 4; q++) {
        const size_t row = (size_t)(i0 + r0 + q) * WFEAT;
        *(float4*)&sen_out[row + c0]     = accA[q];
        *(float4*)&sen_out[row + c0 + 4] = accB[q];
    }
}

// ---------------- K4: partial column max over 128-row slabs ----------------
__global__ __launch_bounds__(128) void k4_pool_partial(const float* __restrict__ sen) {
    const int c = threadIdx.x;
    const int b = blockIdx.x;   // 64 slabs
    float m = NEGINF;
#pragma unroll 8
    for (int r = 0; r < 128; r++)
        m = fmaxf(m, sen[((size_t)b * 128 + r) * WFEAT + c]);
    g_pmax[b * WFEAT + c] = m;
}

// ---------------- K5: final pool + classifier ------------------------------
__global__ __launch_bounds__(128) void k5_head(const float* __restrict__ cls_W,
                                               const float* __restrict__ cls_b,
                                               float* __restrict__ pool_out,
                                               float* __restrict__ lab_out) {
    const int c = threadIdx.x;
    __shared__ float pool[WFEAT];
    float m = NEGINF;
#pragma unroll
    for (int b = 0; b < 64; b++) m = fmaxf(m, g_pmax[b * WFEAT + c]);
    pool[c] = m;
    pool_out[c] = m;
    __syncthreads();
    if (c == 0) {
        float l0 = cls_b[0], l1 = cls_b[1];
#pragma unroll
        for (int k = 0; k < WFEAT; k++) {
            l0 += pool[k] * cls_W[2 * k];
            l1 += pool[k] * cls_W[2 * k + 1];
        }
        const float mm = fmaxf(l0, l1);
        const float e0 = __expf(l0 - mm), e1 = __expf(l1 - mm);
        const float inv = 1.0f / (e0 + e1);
        lab_out[0] = e0 * inv;
        lab_out[1] = e1 * inv;
    }
}

// ---------------- launch ----------------------------------------------------
extern "C" void kernel_launch(void* const* d_in, const int* in_sizes, int n_in,
                              void* d_out, int out_size) {
    const int*   inSen    = (const int*)d_in[0];
    const int*   adj      = (const int*)d_in[1];
    const int*   selfLink = (const int*)d_in[2];
    const float* emb      = (const float*)d_in[3];
    const float* W        = (const float*)d_in[4];
    const float* a_src    = (const float*)d_in[5];
    const float* a_dst    = (const float*)d_in[6];
    const float* cls_W    = (const float*)d_in[7];
    const float* cls_b    = (const float*)d_in[8];

    float* out     = (float*)d_out;
    float* pool_out = out;                                          // 128
    float* att_out  = out + WFEAT;                                  // 8192*8192
    float* sen_out  = att_out + (size_t)N * N;                      // 8192*128
    float* lab_out  = sen_out + (size_t)N * WFEAT;                  // 2

    k1_proj<<<N / 16, 128>>>(inSen, emb, W);
    kf_feat<<<N, 128>>>(a_src, a_dst);
    k2_stats<<<N, 256>>>(adj, selfLink);
    k3_fused<<<N / BI, 256>>>(adj, selfLink, att_out, sen_out);
    k4_pool_partial<<<64, 128>>>(sen_out);
    k5_head<<<1, 128>>>(cls_W, cls_b, pool_out, lab_out);
}

// round 3
// speedup vs baseline: 2.0449x; 2.0449x over previous
#include <cuda_runtime.h>
#include <cuda_bf16.h>
#include <cstdint>
#include <math.h>

#define N 8192
#define EDIM 128
#define WFEAT 128
#define SLOPE 0.01f
#define NEGINF (-3.0e38f)
#define L2E 1.4426950408889634f

// ---------------- device scratch ----------------
__device__ float g_h[(size_t)N * WFEAT];                       // fp32 h
__device__ __nv_bfloat16 g_h16_hi[(size_t)N * WFEAT];          // row-major bf16 hi
__device__ __nv_bfloat16 g_h16_lo[(size_t)N * WFEAT];          // row-major bf16 residual
__device__ float g_fsrc[N];
__device__ float g_fdst[N];
__device__ float g_rowC[N];                                    // -M*log2e - log2(Z)
__device__ float g_pmax[64 * WFEAT];

// ---------------- helpers ----------------
__device__ __forceinline__ uint32_t smem_u32(const void* p) {
    uint32_t a;
    asm("{ .reg .u64 t; cvta.to.shared.u64 t, %1; cvt.u32.u64 %0, t; }" : "=r"(a) : "l"(p));
    return a;
}
__device__ __forceinline__ uint32_t pack2(float lo, float hi) {
    uint32_t r;
    asm("cvt.rn.bf16x2.f32 %0, %1, %2;" : "=r"(r) : "f"(hi), "f"(lo));
    return r;
}
__device__ __forceinline__ void ldsm_x4(uint32_t* r, uint32_t addr) {
    asm volatile("ldmatrix.sync.aligned.m8n8.x4.shared.b16 {%0,%1,%2,%3}, [%4];"
                 : "=r"(r[0]), "=r"(r[1]), "=r"(r[2]), "=r"(r[3]) : "r"(addr));
}
__device__ __forceinline__ void ldsm_x4_t(uint32_t* r, uint32_t addr) {
    asm volatile("ldmatrix.sync.aligned.m8n8.x4.trans.shared.b16 {%0,%1,%2,%3}, [%4];"
                 : "=r"(r[0]), "=r"(r[1]), "=r"(r[2]), "=r"(r[3]) : "r"(addr));
}
__device__ __forceinline__ void mma16816(float* d, const uint32_t* a, const uint32_t* b) {
    asm volatile(
        "mma.sync.aligned.m16n8k16.row.col.f32.bf16.bf16.f32 "
        "{%0,%1,%2,%3}, {%4,%5,%6,%7}, {%8,%9}, {%0,%1,%2,%3};"
        : "+f"(d[0]), "+f"(d[1]), "+f"(d[2]), "+f"(d[3])
        : "r"(a[0]), "r"(a[1]), "r"(a[2]), "r"(a[3]), "r"(b[0]), "r"(b[1]));
}

// ---------------- K1: h = emb[inSen] @ W  (+ bf16 hi/lo row-major) ----------------
__global__ __launch_bounds__(128) void k1_proj(const int* __restrict__ inSen,
                                               const float* __restrict__ emb,
                                               const float* __restrict__ W) {
    __shared__ float Ws[64][128];
    __shared__ float wv[16][64];
    __shared__ int   sIdx[16];

    const int tid = threadIdx.x;
    const int i0  = blockIdx.x * 16;

    if (tid < 16) sIdx[tid] = inSen[i0 + tid];
    __syncthreads();

    float acc[16];
#pragma unroll
    for (int r = 0; r < 16; r++) acc[r] = 0.f;

    const int r  = tid >> 3;
    const int p0 = (tid & 7) * 8;

    for (int kc = 0; kc < EDIM; kc += 64) {
#pragma unroll 8
        for (int dd = 0; dd < 64; dd++)
            Ws[dd][tid] = W[(size_t)(kc + dd) * WFEAT + tid];
        {
            const float* er = emb + (size_t)sIdx[r] * EDIM + kc;
#pragma unroll
            for (int p = 0; p < 8; p++) wv[r][p0 + p] = er[p0 + p];
        }
        __syncthreads();
#pragma unroll 16
        for (int dd = 0; dd < 64; dd++) {
            const float w = Ws[dd][tid];
#pragma unroll
            for (int rr = 0; rr < 16; rr++) acc[rr] += wv[rr][dd] * w;
        }
        __syncthreads();
    }
#pragma unroll
    for (int rr = 0; rr < 16; rr++) {
        const float v = acc[rr];
        const size_t idx = (size_t)(i0 + rr) * WFEAT + tid;
        g_h[idx] = v;
        __nv_bfloat16 hb = __float2bfloat16(v);
        g_h16_hi[idx] = hb;
        g_h16_lo[idx] = __float2bfloat16(v - __bfloat162float(hb));
    }
}

// ---------------- Kf: f_src / f_dst ----------------
__global__ __launch_bounds__(128) void kf_feat(const float* __restrict__ a_src,
                                               const float* __restrict__ a_dst) {
    const int i = blockIdx.x;
    const int tid = threadIdx.x;
    const float hv = g_h[(size_t)i * WFEAT + tid];
    float ps = hv * a_src[tid];
    float pd = hv * a_dst[tid];
#pragma unroll
    for (int off = 16; off > 0; off >>= 1) {
        ps += __shfl_xor_sync(0xffffffffu, ps, off);
        pd += __shfl_xor_sync(0xffffffffu, pd, off);
    }
    __shared__ float rs[4], rd[4];
    const int w = tid >> 5, l = tid & 31;
    if (l == 0) { rs[w] = ps; rd[w] = pd; }
    __syncthreads();
    if (tid == 0) g_fsrc[i] = rs[0] + rs[1] + rs[2] + rs[3];
    if (tid == 1) g_fdst[i] = rd[0] + rd[1] + rd[2] + rd[3];
}

// ---------------- K2: per-row stats -> C = -M*log2e - log2(Z) ----------------
__global__ __launch_bounds__(256) void k2_stats(const int* __restrict__ adj,
                                                const int* __restrict__ selfLinkP) {
    const int i   = blockIdx.x;
    const int tid = threadIdx.x;
    const int selfLink = *selfLinkP;
    const float si = g_fsrc[i];

    float v[32];
    float tm = NEGINF;
    const int4* arow = (const int4*)(adj + (size_t)i * N);
#pragma unroll
    for (int k = 0; k < 8; k++) {
        const int idx4 = tid + (k << 8);
        const int4 a = __ldg(arow + idx4);
        const int j0 = idx4 << 2;
        int aa[4] = {a.x, a.y, a.z, a.w};
#pragma unroll
        for (int p = 0; p < 4; p++) {
            const int j = j0 + p;
            const int m = aa[p] + ((j == i) ? selfLink : 0);
            const float x = si + __ldg(&g_fdst[j]);
            const float lk = fmaxf(x, SLOPE * x);
            const float val = (m > 0) ? lk : -1e9f;
            v[(k << 2) + p] = val;
            tm = fmaxf(tm, val);
        }
    }
    __shared__ float smax[8];
#pragma unroll
    for (int off = 16; off > 0; off >>= 1) tm = fmaxf(tm, __shfl_xor_sync(0xffffffffu, tm, off));
    if ((tid & 31) == 0) smax[tid >> 5] = tm;
    __syncthreads();
    if (tid < 32) {
        float z = (tid < 8) ? smax[tid] : NEGINF;
#pragma unroll
        for (int off = 4; off > 0; off >>= 1) z = fmaxf(z, __shfl_xor_sync(0xffffffffu, z, off));
        if (tid == 0) smax[0] = z;
    }
    __syncthreads();
    const float M = smax[0];

    float ts = 0.f;
#pragma unroll
    for (int k = 0; k < 32; k++) ts += __expf(v[k] - M);
    __shared__ float ssum[8];
#pragma unroll
    for (int off = 16; off > 0; off >>= 1) ts += __shfl_xor_sync(0xffffffffu, ts, off);
    if ((tid & 31) == 0) ssum[tid >> 5] = ts;
    __syncthreads();
    if (tid == 0) {
        float S = 0.f;
#pragma unroll
        for (int w = 0; w < 8; w++) S += ssum[w];
        g_rowC[i] = fmaf(-M, L2E, -__log2f(S));
    }
}

// ---------------- K3: fused attention + HMMA GEMM ----------------
// 64-row strip per CTA, K chunks of 64, 256 threads (8 warps = 2x4 warp grid).
// smem (dynamic): A_hi[64][72] A_lo[64][72] bf16, B_hi[64][136] B_lo[64][136] bf16.
#define SA_STRIDE 72
#define SB_STRIDE 136
#define OFF_AH 0
#define OFF_AL (64 * SA_STRIDE * 2)                 // 9216
#define OFF_BH (2 * 64 * SA_STRIDE * 2)             // 18432
#define OFF_BL (OFF_BH + 64 * SB_STRIDE * 2)        // 35840
#define K3_SMEM (OFF_BL + 64 * SB_STRIDE * 2)       // 53248

__global__ __launch_bounds__(256, 1) void k3_hmma(const int* __restrict__ adj,
                                                  const int* __restrict__ selfLinkP,
                                                  float* __restrict__ att_out,
                                                  float* __restrict__ sen_out) {
    extern __shared__ char smem[];
    const uint32_t sb = smem_u32(smem);

    const int tid = threadIdx.x;
    const int wid = tid >> 5;
    const int lane = tid & 31;
    const int i0 = blockIdx.x * 64;
    const int selfLink = *selfLinkP;

    // stage-A mapping: 4 threads per row, 16 cols each
    const int arow = tid >> 2;
    const int acq  = tid & 3;          // column quarter
    const int gi = i0 + arow;
    const float fs = g_fsrc[gi];
    const float Cr = g_rowC[gi];
    const int* adj_row = adj + (size_t)gi * N;
    float*     att_row = att_out + (size_t)gi * N;

    // MMA warp tiling: warp_m in {0,1} (32 rows), warp_n in {0..3} (32 cols)
    const int warp_m = wid >> 2;
    const int warp_n = wid & 3;

    // ldmatrix lane addresses (offsets within chunk tiles)
    const int lrow = lane & 15;
    const int lgrp = lane >> 4;
    // A: row = warp_m*32 + mf*16 + lrow, col = ks*16 + lgrp*8
    const uint32_t a_base = sb + ((warp_m * 32 + lrow) * SA_STRIDE + lgrp * 8) * 2;
    // B: row(k) = ks*16 + lrow, col = warp_n*32 + pair*16 + lgrp*8
    const uint32_t b_base = sb + OFF_BH + (lrow * SB_STRIDE + warp_n * 32 + lgrp * 8) * 2;

    float acc[2][4][4];
#pragma unroll
    for (int mf = 0; mf < 2; mf++)
#pragma unroll
        for (int nf = 0; nf < 4; nf++)
#pragma unroll
            for (int q = 0; q < 4; q++) acc[mf][nf][q] = 0.f;

    const uint4* __restrict__ gBh = (const uint4*)g_h16_hi;
    const uint4* __restrict__ gBl = (const uint4*)g_h16_lo;

    for (int c = 0; c < N / 64; c++) {
        const int jbase = c * 64;
        __syncthreads();   // previous MMA finished reading smem

        // --- load B tile: h[jbase..jbase+63][0..127] hi/lo ---
#pragma unroll
        for (int p = 0; p < 4; p++) {
            const int e = tid + p * 256;         // 0..1023
            const int br = e >> 4;               // row 0..63
            const int bc = e & 15;               // uint4 col 0..15
            const uint32_t dst = (br * SB_STRIDE + bc * 8) * 2;
            const size_t src = (size_t)(jbase + br) * 16 + bc;
            *(uint4*)(smem + OFF_BH + dst) = __ldg(gBh + src);
            *(uint4*)(smem + OFF_BL + dst) = __ldg(gBl + src);
        }

        // --- stage A: 16 attention values per thread ---
#pragma unroll
        for (int g = 0; g < 4; g++) {
            const int jcol = acq * 16 + g * 4;
            const int jg = jbase + jcol;
            const int4 a4 = __ldg((const int4*)(adj_row + jg));
            const float4 d4 = *(const float4*)&g_fdst[jg];

            float v0 = fs + d4.x, v1 = fs + d4.y, v2 = fs + d4.z, v3 = fs + d4.w;
            v0 = fmaxf(v0, SLOPE * v0);
            v1 = fmaxf(v1, SLOPE * v1);
            v2 = fmaxf(v2, SLOPE * v2);
            v3 = fmaxf(v3, SLOPE * v3);
            const int m0 = a4.x + ((jg + 0) == gi ? selfLink : 0);
            const int m1 = a4.y + ((jg + 1) == gi ? selfLink : 0);
            const int m2 = a4.z + ((jg + 2) == gi ? selfLink : 0);
            const int m3 = a4.w + ((jg + 3) == gi ? selfLink : 0);
            float r0 = (m0 > 0) ? fmaf(v0, L2E, Cr) : -1e30f;
            float r1 = (m1 > 0) ? fmaf(v1, L2E, Cr) : -1e30f;
            float r2 = (m2 > 0) ? fmaf(v2, L2E, Cr) : -1e30f;
            float r3 = (m3 > 0) ? fmaf(v3, L2E, Cr) : -1e30f;
            float a0, a1, a2, a3;
            asm("ex2.approx.f32 %0, %1;" : "=f"(a0) : "f"(r0));
            asm("ex2.approx.f32 %0, %1;" : "=f"(a1) : "f"(r1));
            asm("ex2.approx.f32 %0, %1;" : "=f"(a2) : "f"(r2));
            asm("ex2.approx.f32 %0, %1;" : "=f"(a3) : "f"(r3));

            *(float4*)(att_row + jg) = make_float4(a0, a1, a2, a3);

            const uint32_t h01 = pack2(a0, a1);
            const uint32_t h23 = pack2(a2, a3);
            const float l0 = a0 - __uint_as_float(h01 << 16);
            const float l1 = a1 - __uint_as_float(h01 & 0xFFFF0000u);
            const float l2 = a2 - __uint_as_float(h23 << 16);
            const float l3 = a3 - __uint_as_float(h23 & 0xFFFF0000u);
            const uint32_t q01 = pack2(l0, l1);
            const uint32_t q23 = pack2(l2, l3);
            const uint32_t ao = (arow * SA_STRIDE + jcol) * 2;
            *(uint2*)(smem + OFF_AH + ao) = make_uint2(h01, h23);
            *(uint2*)(smem + OFF_AL + ao) = make_uint2(q01, q23);
        }
        __syncthreads();   // tiles ready

        // --- MMA over chunk: 4 k16 steps ---
#pragma unroll
        for (int ks = 0; ks < 4; ks++) {
            uint32_t ah[2][4], al[2][4], bh[2][4], bl[2][4];
#pragma unroll
            for (int mf = 0; mf < 2; mf++) {
                const uint32_t aoff = (mf * 16 * SA_STRIDE + ks * 16) * 2;
                ldsm_x4(ah[mf], a_base + aoff);
                ldsm_x4(al[mf], a_base + OFF_AL + aoff);
            }
#pragma unroll
            for (int pr = 0; pr < 2; pr++) {
                const uint32_t boff = (ks * 16 * SB_STRIDE + pr * 16) * 2;
                ldsm_x4_t(bh[pr], b_base + boff);
                ldsm_x4_t(bl[pr], b_base + (OFF_BL - OFF_BH) + boff);
            }
#pragma unroll
            for (int mf = 0; mf < 2; mf++)
#pragma unroll
                for (int nf = 0; nf < 4; nf++) {
                    const uint32_t* bhp = &bh[nf >> 1][(nf & 1) * 2];
                    const uint32_t* blp = &bl[nf >> 1][(nf & 1) * 2];
                    mma16816(acc[mf][nf], ah[mf], bhp);
                    mma16816(acc[mf][nf], al[mf], bhp);
                    mma16816(acc[mf][nf], ah[mf], blp);
                }
        }
    }

    // --- epilogue: write sentence tile ---
    const int grp = lane >> 2;
    const int tig = lane & 3;
#pragma unroll
    for (int mf = 0; mf < 2; mf++)
#pragma unroll
        for (int nf = 0; nf < 4; nf++) {
            const int row0 = i0 + warp_m * 32 + mf * 16 + grp;
            const int col  = warp_n * 32 + nf * 8 + tig * 2;
            *(float2*)&sen_out[(size_t)row0 * WFEAT + col] =
                make_float2(acc[mf][nf][0], acc[mf][nf][1]);
            *(float2*)&sen_out[(size_t)(row0 + 8) * WFEAT + col] =
                make_float2(acc[mf][nf][2], acc[mf][nf][3]);
        }
}

// ---------------- K4: partial column max ----------------
__global__ __launch_bounds__(128) void k4_pool_partial(const float* __restrict__ sen) {
    const int c = threadIdx.x;
    const int b = blockIdx.x;
    float m = NEGINF;
#pragma unroll 8
    for (int r = 0; r < 128; r++)
        m = fmaxf(m, sen[((size_t)b * 128 + r) * WFEAT + c]);
    g_pmax[b * WFEAT + c] = m;
}

// ---------------- K5: final pool + classifier ----------------
__global__ __launch_bounds__(128) void k5_head(const float* __restrict__ cls_W,
                                               const float* __restrict__ cls_b,
                                               float* __restrict__ pool_out,
                                               float* __restrict__ lab_out) {
    const int c = threadIdx.x;
    __shared__ float pool[WFEAT];
    float m = NEGINF;
#pragma unroll
    for (int b = 0; b < 64; b++) m = fmaxf(m, g_pmax[b * WFEAT + c]);
    pool[c] = m;
    pool_out[c] = m;
    __syncthreads();
    if (c == 0) {
        float l0 = cls_b[0], l1 = cls_b[1];
#pragma unroll
        for (int k = 0; k < WFEAT; k++) {
            l0 += pool[k] * cls_W[2 * k];
            l1 += pool[k] * cls_W[2 * k + 1];
        }
        const float mm = fmaxf(l0, l1);
        const float e0 = __expf(l0 - mm), e1 = __expf(l1 - mm);
        const float inv = 1.0f / (e0 + e1);
        lab_out[0] = e0 * inv;
        lab_out[1] = e1 * inv;
    }
}

// ---------------- launch ----------------
extern "C" void kernel_launch(void* const* d_in, const int* in_sizes, int n_in,
                              void* d_out, int out_size) {
    const int*   inSen    = (const int*)d_in[0];
    const int*   adj      = (const int*)d_in[1];
    const int*   selfLink = (const int*)d_in[2];
    const float* emb      = (const float*)d_in[3];
    const float* W        = (const float*)d_in[4];
    const float* a_src    = (const float*)d_in[5];
    const float* a_dst    = (const float*)d_in[6];
    const float* cls_W    = (const float*)d_in[7];
    const float* cls_b    = (const float*)d_in[8];

    float* out      = (float*)d_out;
    float* pool_out = out;
    float* att_out  = out + WFEAT;
    float* sen_out  = att_out + (size_t)N * N;
    float* lab_out  = sen_out + (size_t)N * WFEAT;

    static int configured = 0;
    if (!configured) {
        cudaFuncSetAttribute(k3_hmma, cudaFuncAttributeMaxDynamicSharedMemorySize, K3_SMEM);
        configured = 1;
    }

    k1_proj<<<N / 16, 128>>>(inSen, emb, W);
    kf_feat<<<N, 128>>>(a_src, a_dst);
    k2_stats<<<N, 256>>>(adj, selfLink);
    k3_hmma<<<N / 64, 256, K3_SMEM>>>(adj, selfLink, att_out, sen_out);
    k4_pool_partial<<<64, 128>>>(sen_out);
    k5_head<<<1, 128>>>(cls_W, cls_b, pool_out, lab_out);
}

// round 5
// speedup vs baseline: 2.4477x; 1.1970x over previous
#include <cuda_runtime.h>
#include <cuda_bf16.h>
#include <cstdint>
#include <math.h>

#define N 8192
#define EDIM 128
#define WFEAT 128
#define SLOPE 0.01f
#define NEGINF (-3.0e38f)
#define L2E 1.4426950408889634f

// ---------------- device scratch ----------------
__device__ float g_h[(size_t)N * WFEAT];
__device__ __nv_bfloat16 g_h16_hi[(size_t)N * WFEAT];
__device__ __nv_bfloat16 g_h16_lo[(size_t)N * WFEAT];
__device__ float g_fsrc[N];
__device__ float g_fdst[N];
__device__ float g_rowC[N];
__device__ float g_pmax[64 * WFEAT];

// ---------------- helpers ----------------
__device__ __forceinline__ uint32_t smem_u32(const void* p) {
    uint32_t a;
    asm("{ .reg .u64 t; cvta.to.shared.u64 t, %1; cvt.u32.u64 %0, t; }" : "=r"(a) : "l"(p));
    return a;
}
__device__ __forceinline__ uint32_t pack2(float lo, float hi) {
    uint32_t r;
    asm("cvt.rn.bf16x2.f32 %0, %1, %2;" : "=r"(r) : "f"(hi), "f"(lo));
    return r;
}
__device__ __forceinline__ void cp16(uint32_t dst, const void* src) {
    asm volatile("cp.async.cg.shared.global [%0], [%1], 16;" :: "r"(dst), "l"(src));
}
__device__ __forceinline__ void cp_commit() {
    asm volatile("cp.async.commit_group;");
}
__device__ __forceinline__ void cp_wait0() {
    asm volatile("cp.async.wait_group 0;");
}
__device__ __forceinline__ void ldsm_x4(uint32_t* r, uint32_t addr) {
    asm volatile("ldmatrix.sync.aligned.m8n8.x4.shared.b16 {%0,%1,%2,%3}, [%4];"
                 : "=r"(r[0]), "=r"(r[1]), "=r"(r[2]), "=r"(r[3]) : "r"(addr));
}
__device__ __forceinline__ void ldsm_x4_t(uint32_t* r, uint32_t addr) {
    asm volatile("ldmatrix.sync.aligned.m8n8.x4.trans.shared.b16 {%0,%1,%2,%3}, [%4];"
                 : "=r"(r[0]), "=r"(r[1]), "=r"(r[2]), "=r"(r[3]) : "r"(addr));
}
__device__ __forceinline__ void mma16816(float* d, const uint32_t* a, const uint32_t* b) {
    asm volatile(
        "mma.sync.aligned.m16n8k16.row.col.f32.bf16.bf16.f32 "
        "{%0,%1,%2,%3}, {%4,%5,%6,%7}, {%8,%9}, {%0,%1,%2,%3};"
        : "+f"(d[0]), "+f"(d[1]), "+f"(d[2]), "+f"(d[3])
        : "r"(a[0]), "r"(a[1]), "r"(a[2]), "r"(a[3]), "r"(b[0]), "r"(b[1]));
}

// ---------------- K1: h = emb[inSen] @ W (+ bf16 hi/lo) ----------------
__global__ __launch_bounds__(128) void k1_proj(const int* __restrict__ inSen,
                                               const float* __restrict__ emb,
                                               const float* __restrict__ W) {
    __shared__ float Ws[64][128];
    __shared__ float wv[16][64];
    __shared__ int   sIdx[16];

    const int tid = threadIdx.x;
    const int i0  = blockIdx.x * 16;

    if (tid < 16) sIdx[tid] = inSen[i0 + tid];
    __syncthreads();

    float acc[16];
#pragma unroll
    for (int r = 0; r < 16; r++) acc[r] = 0.f;

    const int r  = tid >> 3;
    const int p0 = (tid & 7) * 8;

    for (int kc = 0; kc < EDIM; kc += 64) {
#pragma unroll 8
        for (int dd = 0; dd < 64; dd++)
            Ws[dd][tid] = W[(size_t)(kc + dd) * WFEAT + tid];
        {
            const float* er = emb + (size_t)sIdx[r] * EDIM + kc;
#pragma unroll
            for (int p = 0; p < 8; p++) wv[r][p0 + p] = er[p0 + p];
        }
        __syncthreads();
#pragma unroll 16
        for (int dd = 0; dd < 64; dd++) {
            const float w = Ws[dd][tid];
#pragma unroll
            for (int rr = 0; rr < 16; rr++) acc[rr] += wv[rr][dd] * w;
        }
        __syncthreads();
    }
#pragma unroll
    for (int rr = 0; rr < 16; rr++) {
        const float v = acc[rr];
        const size_t idx = (size_t)(i0 + rr) * WFEAT + tid;
        g_h[idx] = v;
        __nv_bfloat16 hb = __float2bfloat16(v);
        g_h16_hi[idx] = hb;
        g_h16_lo[idx] = __float2bfloat16(v - __bfloat162float(hb));
    }
}

// ---------------- Kf ----------------
__global__ __launch_bounds__(128) void kf_feat(const float* __restrict__ a_src,
                                               const float* __restrict__ a_dst) {
    const int i = blockIdx.x;
    const int tid = threadIdx.x;
    const float hv = g_h[(size_t)i * WFEAT + tid];
    float ps = hv * a_src[tid];
    float pd = hv * a_dst[tid];
#pragma unroll
    for (int off = 16; off > 0; off >>= 1) {
        ps += __shfl_xor_sync(0xffffffffu, ps, off);
        pd += __shfl_xor_sync(0xffffffffu, pd, off);
    }
    __shared__ float rs[4], rd[4];
    const int w = tid >> 5, l = tid & 31;
    if (l == 0) { rs[w] = ps; rd[w] = pd; }
    __syncthreads();
    if (tid == 0) g_fsrc[i] = rs[0] + rs[1] + rs[2] + rs[3];
    if (tid == 1) g_fdst[i] = rd[0] + rd[1] + rd[2] + rd[3];
}

// ---------------- K2: row stats ----------------
__global__ __launch_bounds__(256) void k2_stats(const int* __restrict__ adj,
                                                const int* __restrict__ selfLinkP) {
    const int i   = blockIdx.x;
    const int tid = threadIdx.x;
    const int selfLink = *selfLinkP;
    const float si = g_fsrc[i];

    float v[32];
    float tm = NEGINF;
    const int4* arow = (const int4*)(adj + (size_t)i * N);
#pragma unroll
    for (int k = 0; k < 8; k++) {
        const int idx4 = tid + (k << 8);
        const int4 a = __ldg(arow + idx4);
        const int j0 = idx4 << 2;
        int aa[4] = {a.x, a.y, a.z, a.w};
#pragma unroll
        for (int p = 0; p < 4; p++) {
            const int j = j0 + p;
            const int m = aa[p] + ((j == i) ? selfLink : 0);
            const float x = si + __ldg(&g_fdst[j]);
            const float lk = fmaxf(x, SLOPE * x);
            const float val = (m > 0) ? lk : -1e9f;
            v[(k << 2) + p] = val;
            tm = fmaxf(tm, val);
        }
    }
    __shared__ float smax[8];
#pragma unroll
    for (int off = 16; off > 0; off >>= 1) tm = fmaxf(tm, __shfl_xor_sync(0xffffffffu, tm, off));
    if ((tid & 31) == 0) smax[tid >> 5] = tm;
    __syncthreads();
    if (tid < 32) {
        float z = (tid < 8) ? smax[tid] : NEGINF;
#pragma unroll
        for (int off = 4; off > 0; off >>= 1) z = fmaxf(z, __shfl_xor_sync(0xffffffffu, z, off));
        if (tid == 0) smax[0] = z;
    }
    __syncthreads();
    const float M = smax[0];

    float ts = 0.f;
#pragma unroll
    for (int k = 0; k < 32; k++) ts += __expf(v[k] - M);
    __shared__ float ssum[8];
#pragma unroll
    for (int off = 16; off > 0; off >>= 1) ts += __shfl_xor_sync(0xffffffffu, ts, off);
    if ((tid & 31) == 0) ssum[tid >> 5] = ts;
    __syncthreads();
    if (tid == 0) {
        float S = 0.f;
#pragma unroll
        for (int w = 0; w < 8; w++) S += ssum[w];
        g_rowC[i] = fmaf(-M, L2E, -__log2f(S));
    }
}

// ---------------- K3: pipelined fused attention + HMMA ----------------
// smem layout (bytes):
//  fdst:                 [0, 32768)
//  adj[2]:               [32768, 32768+2*17408)         272B/row
//  B hi/lo [2]:          [67584, 67584+4*17408)         buffer b: hi at b*2*B_BUF, lo at b*2*B_BUF+B_BUF
//  A hi/lo:              [137216, 137216+2*9216)        stride 72 bf16
#define OFF_FDST 0
#define OFF_ADJ 32768
#define ADJ_BUF 17408
#define OFF_B 67584
#define B_BUF 17408
#define SB_STRIDE 136
#define OFF_A 137216
#define SA_STRIDE 72
#define A_BUF 9216
#define K3_SMEM (OFF_A + 2 * A_BUF)          // 155648
#define NCH (N / 64)

__global__ __launch_bounds__(256, 1) void k3_hmma(const int* __restrict__ adj,
                                                  const int* __restrict__ selfLinkP,
                                                  float* __restrict__ att_out,
                                                  float* __restrict__ sen_out) {
    extern __shared__ char smem[];
    const uint32_t sb = smem_u32(smem);

    const int tid = threadIdx.x;
    const int wid = tid >> 5;
    const int lane = tid & 31;
    const int i0 = blockIdx.x * 64;
    const int selfLink = *selfLinkP;

    // stage-A mapping: 4 threads per row, 16 cols each
    const int arow = tid >> 2;
    const int acq  = tid & 3;
    const int gi = i0 + arow;
    const float fs = g_fsrc[gi];
    const float Cr = g_rowC[gi];
    float* att_row = att_out + (size_t)gi * N;

    // cp.async mapping
    const int cprow = tid >> 4;
    const int cpseg = tid & 15;

    // preload fdst (32KB): 8 x 16B per thread
#pragma unroll
    for (int p = 0; p < 8; p++) {
        const int s = tid + p * 256;
        cp16(sb + OFF_FDST + s * 16, (const char*)g_fdst + s * 16);
    }

    // prefetch chunk 0 into buffer 0 (hi at OFF_B, lo at OFF_B + B_BUF)
    {
        const int jb = 0;
#pragma unroll
        for (int p = 0; p < 4; p++) {
            const int row = cprow + p * 16;
            cp16(sb + OFF_ADJ + row * 272 + cpseg * 16,
                 adj + (size_t)(i0 + row) * N + jb + cpseg * 4);
            cp16(sb + OFF_B + row * 272 + cpseg * 16,
                 (const char*)g_h16_hi + ((size_t)(jb + row) * WFEAT + cpseg * 8) * 2);
            cp16(sb + OFF_B + B_BUF + row * 272 + cpseg * 16,
                 (const char*)g_h16_lo + ((size_t)(jb + row) * WFEAT + cpseg * 8) * 2);
        }
    }
    cp_commit();

    // MMA warp tiling
    const int warp_m = wid >> 2;
    const int warp_n = wid & 3;
    const int lrow = lane & 15;
    const int lgrp = lane >> 4;
    const uint32_t a_base = sb + OFF_A + ((warp_m * 32 + lrow) * SA_STRIDE + lgrp * 8) * 2;
    const uint32_t b_lane_off = (lrow * SB_STRIDE + warp_n * 32 + lgrp * 8) * 2;

    float acc[2][4][4];
#pragma unroll
    for (int mf = 0; mf < 2; mf++)
#pragma unroll
        for (int nf = 0; nf < 4; nf++)
#pragma unroll
            for (int q = 0; q < 4; q++) acc[mf][nf][q] = 0.f;

    for (int c = 0; c < NCH; c++) {
        const int b = c & 1;
        const int jbase = c * 64;

        cp_wait0();
        __syncthreads();   // chunk-c data visible; MMA(c-1) done everywhere

        // --- stage A: 16 attention values per thread ---
#pragma unroll
        for (int g = 0; g < 4; g++) {
            const int jcol = acq * 16 + g * 4;
            const int jg = jbase + jcol;
            const int4 a4 = *(const int4*)(smem + OFF_ADJ + b * ADJ_BUF + arow * 272 + jcol * 4);
            const float4 d4 = *(const float4*)(smem + OFF_FDST + jg * 4);

            float v0 = fs + d4.x, v1 = fs + d4.y, v2 = fs + d4.z, v3 = fs + d4.w;
            v0 = fmaxf(v0, SLOPE * v0);
            v1 = fmaxf(v1, SLOPE * v1);
            v2 = fmaxf(v2, SLOPE * v2);
            v3 = fmaxf(v3, SLOPE * v3);
            const int m0 = a4.x + ((jg + 0) == gi ? selfLink : 0);
            const int m1 = a4.y + ((jg + 1) == gi ? selfLink : 0);
            const int m2 = a4.z + ((jg + 2) == gi ? selfLink : 0);
            const int m3 = a4.w + ((jg + 3) == gi ? selfLink : 0);
            float r0 = (m0 > 0) ? fmaf(v0, L2E, Cr) : -1e30f;
            float r1 = (m1 > 0) ? fmaf(v1, L2E, Cr) : -1e30f;
            float r2 = (m2 > 0) ? fmaf(v2, L2E, Cr) : -1e30f;
            float r3 = (m3 > 0) ? fmaf(v3, L2E, Cr) : -1e30f;
            float a0, a1, a2, a3;
            asm("ex2.approx.f32 %0, %1;" : "=f"(a0) : "f"(r0));
            asm("ex2.approx.f32 %0, %1;" : "=f"(a1) : "f"(r1));
            asm("ex2.approx.f32 %0, %1;" : "=f"(a2) : "f"(r2));
            asm("ex2.approx.f32 %0, %1;" : "=f"(a3) : "f"(r3));

            *(float4*)(att_row + jg) = make_float4(a0, a1, a2, a3);

            const uint32_t h01 = pack2(a0, a1);
            const uint32_t h23 = pack2(a2, a3);
            const float l0 = a0 - __uint_as_float(h01 << 16);
            const float l1 = a1 - __uint_as_float(h01 & 0xFFFF0000u);
            const float l2 = a2 - __uint_as_float(h23 << 16);
            const float l3 = a3 - __uint_as_float(h23 & 0xFFFF0000u);
            const uint32_t q01 = pack2(l0, l1);
            const uint32_t q23 = pack2(l2, l3);
            const uint32_t ao = (arow * SA_STRIDE + jcol) * 2;
            *(uint2*)(smem + OFF_A + ao)         = make_uint2(h01, h23);
            *(uint2*)(smem + OFF_A + A_BUF + ao) = make_uint2(q01, q23);
        }

        // --- prefetch chunk c+1 into other buffer (overlaps MMA below) ---
        if (c + 1 < NCH) {
            const int bn = 1 - b;
            const int jb = (c + 1) * 64;
#pragma unroll
            for (int p = 0; p < 4; p++) {
                const int row = cprow + p * 16;
                cp16(sb + OFF_ADJ + bn * ADJ_BUF + row * 272 + cpseg * 16,
                     adj + (size_t)(i0 + row) * N + jb + cpseg * 4);
                cp16(sb + OFF_B + bn * 2 * B_BUF + row * 272 + cpseg * 16,
                     (const char*)g_h16_hi + ((size_t)(jb + row) * WFEAT + cpseg * 8) * 2);
                cp16(sb + OFF_B + bn * 2 * B_BUF + B_BUF + row * 272 + cpseg * 16,
                     (const char*)g_h16_lo + ((size_t)(jb + row) * WFEAT + cpseg * 8) * 2);
            }
        }
        cp_commit();

        __syncthreads();   // A tile + B/adj(c) stable for MMA

        // --- MMA over chunk: 4 k16 steps ---
        const uint32_t bh_base = sb + OFF_B + b * 2 * B_BUF + b_lane_off;
        const uint32_t bl_base = bh_base + B_BUF;
#pragma unroll
        for (int ks = 0; ks < 4; ks++) {
            uint32_t ah[2][4], al[2][4], bh[2][4], bl[2][4];
#pragma unroll
            for (int mf = 0; mf < 2; mf++) {
                const uint32_t aoff = (mf * 16 * SA_STRIDE + ks * 16) * 2;
                ldsm_x4(ah[mf], a_base + aoff);
                ldsm_x4(al[mf], a_base + A_BUF + aoff);
            }
#pragma unroll
            for (int pr = 0; pr < 2; pr++) {
                const uint32_t boff = (ks * 16 * SB_STRIDE + pr * 16) * 2;
                ldsm_x4_t(bh[pr], bh_base + boff);
                ldsm_x4_t(bl[pr], bl_base + boff);
            }
#pragma unroll
            for (int mf = 0; mf < 2; mf++)
#pragma unroll
                for (int nf = 0; nf < 4; nf++) {
                    const uint32_t* bhp = &bh[nf >> 1][(nf & 1) * 2];
                    const uint32_t* blp = &bl[nf >> 1][(nf & 1) * 2];
                    mma16816(acc[mf][nf], ah[mf], bhp);
                    mma16816(acc[mf][nf], al[mf], bhp);
                    mma16816(acc[mf][nf], ah[mf], blp);
                }
        }
    }

    // --- epilogue ---
    const int grp = lane >> 2;
    const int tig = lane & 3;
#pragma unroll
    for (int mf = 0; mf < 2; mf++)
#pragma unroll
        for (int nf = 0; nf < 4; nf++) {
            const int row0 = i0 + warp_m * 32 + mf * 16 + grp;
            const int col  = warp_n * 32 + nf * 8 + tig * 2;
            *(float2*)&sen_out[(size_t)row0 * WFEAT + col] =
                make_float2(acc[mf][nf][0], acc[mf][nf][1]);
            *(float2*)&sen_out[(size_t)(row0 + 8) * WFEAT + col] =
                make_float2(acc[mf][nf][2], acc[mf][nf][3]);
        }
}

// ---------------- K4 ----------------
__global__ __launch_bounds__(128) void k4_pool_partial(const float* __restrict__ sen) {
    const int c = threadIdx.x;
    const int b = blockIdx.x;
    float m = NEGINF;
#pragma unroll 8
    for (int r = 0; r < 128; r++)
        m = fmaxf(m, sen[((size_t)b * 128 + r) * WFEAT + c]);
    g_pmax[b * WFEAT + c] = m;
}

// ---------------- K5 ----------------
__global__ __launch_bounds__(128) void k5_head(const float* __restrict__ cls_W,
                                               const float* __restrict__ cls_b,
                                               float* __restrict__ pool_out,
                                               float* __restrict__ lab_out) {
    const int c = threadIdx.x;
    __shared__ float pool[WFEAT];
    float m = NEGINF;
#pragma unroll
    for (int b = 0; b < 64; b++) m = fmaxf(m, g_pmax[b * WFEAT + c]);
    pool[c] = m;
    pool_out[c] = m;
    __syncthreads();
    if (c == 0) {
        float l0 = cls_b[0], l1 = cls_b[1];
#pragma unroll
        for (int k = 0; k < WFEAT; k++) {
            l0 += pool[k] * cls_W[2 * k];
            l1 += pool[k] * cls_W[2 * k + 1];
        }
        const float mm = fmaxf(l0, l1);
        const float e0 = __expf(l0 - mm), e1 = __expf(l1 - mm);
        const float inv = 1.0f / (e0 + e1);
        lab_out[0] = e0 * inv;
        lab_out[1] = e1 * inv;
    }
}

// ---------------- launch ----------------
extern "C" void kernel_launch(void* const* d_in, const int* in_sizes, int n_in,
                              void* d_out, int out_size) {
    const int*   inSen    = (const int*)d_in[0];
    const int*   adj      = (const int*)d_in[1];
    const int*   selfLink = (const int*)d_in[2];
    const float* emb      = (const float*)d_in[3];
    const float* W        = (const float*)d_in[4];
    const float* a_src    = (const float*)d_in[5];
    const float* a_dst    = (const float*)d_in[6];
    const float* cls_W    = (const float*)d_in[7];
    const float* cls_b    = (const float*)d_in[8];

    float* out      = (float*)d_out;
    float* pool_out = out;
    float* att_out  = out + WFEAT;
    float* sen_out  = att_out + (size_t)N * N;
    float* lab_out  = sen_out + (size_t)N * WFEAT;

    static int configured = 0;
    if (!configured) {
        cudaFuncSetAttribute(k3_hmma, cudaFuncAttributeMaxDynamicSharedMemorySize, K3_SMEM);
        configured = 1;
    }

    k1_proj<<<N / 16, 128>>>(inSen, emb, W);
    kf_feat<<<N, 128>>>(a_src, a_dst);
    k2_stats<<<N, 256>>>(adj, selfLink);
    k3_hmma<<<N / 64, 256, K3_SMEM>>>(adj, selfLink, att_out, sen_out);
    k4_pool_partial<<<64, 128>>>(sen_out);
    k5_head<<<1, 128>>>(cls_W, cls_b, pool_out, lab_out);
}